// round 2
// baseline (speedup 1.0000x reference)
#include <cuda_runtime.h>
#include <math.h>

#define B_  16
#define T_  32
#define S_  128
#define F_  3
#define H_  256
#define NH_ 8
#define DK_ 32
#define TP_ 4
#define R_  (B_*S_)   // 2048 rows per GEMM

// ---------------- device scratch (no allocations allowed) ----------------
__device__ float g_eh[R_*H_];
__device__ float g_ec[R_*H_];
__device__ float g_dh[R_*H_];
__device__ float g_qkv[R_*3*H_];     // [q|k|v] per row, stride 768
__device__ float g_ctx[R_*H_];
__device__ float g_acat[R_*3*H_];    // assembled GEMM input (max K=768)
__device__ float g_z[R_*4*H_];       // gates
__device__ float g_code[R_*H_];
__device__ float g_outv[R_];
__device__ float g_Wqkv_e[H_*3*H_];
__device__ float g_Wqkv_d[H_*3*H_];

__device__ __forceinline__ float sigmoidf_(float x) { return 1.0f / (1.0f + __expf(-x)); }

__device__ __forceinline__ float warp_sum(float v) {
    v += __shfl_xor_sync(0xffffffffu, v, 16);
    v += __shfl_xor_sync(0xffffffffu, v, 8);
    v += __shfl_xor_sync(0xffffffffu, v, 4);
    v += __shfl_xor_sync(0xffffffffu, v, 2);
    v += __shfl_xor_sync(0xffffffffu, v, 1);
    return v;
}

// ---------------- SGEMM: C[M,N] = A[M,K] @ B[K,N] (+bias)(+sigmoid) ----------------
// BM=128, BN=64, BK=16, 256 threads, micro-tile 8x4 with strided mapping
// (m = ty + 16*i, n = tx + 16*j) -> conflict-free LDS reads; As padded -> conflict-free STS.
template<int ACT, bool HASBIAS>
__global__ __launch_bounds__(256)
void sgemm_kernel(const float* __restrict__ A, const float* __restrict__ Bm,
                  const float* __restrict__ bias, float* __restrict__ C,
                  int M, int N, int K) {
    const int BM = 128, BN = 64, BK = 16;
    __shared__ float As[BK][BM + 2];   // pad 2 -> store stride 130 (2k+m banks, conflict-free)
    __shared__ float Bs[BK][BN];

    int tid = threadIdx.x;
    int bm = blockIdx.y * BM;
    int bn = blockIdx.x * BN;
    int ty = tid >> 4;        // 0..15
    int tx = tid & 15;        // 0..15

    float acc[8][4];
#pragma unroll
    for (int i = 0; i < 8; i++)
#pragma unroll
        for (int j = 0; j < 4; j++) acc[i][j] = 0.0f;

    for (int k0 = 0; k0 < K; k0 += BK) {
        // load A tile: 2048 elems, 8/thread. tid -> (m = idx>>4, k = idx&15)
#pragma unroll
        for (int i = 0; i < 8; i++) {
            int idx = tid + i * 256;
            int m = idx >> 4;
            int k = idx & 15;
            int gk = k0 + k;
            float v = 0.0f;
            int gm = bm + m;
            if (gk < K && gm < M) v = A[(size_t)gm * K + gk];
            As[k][m] = v;
        }
        // load B tile: 1024 elems, 4/thread. tid -> (k = idx>>6, n = idx&63)
#pragma unroll
        for (int i = 0; i < 4; i++) {
            int idx = tid + i * 256;
            int k = idx >> 6;
            int n = idx & 63;
            int gk = k0 + k;
            float v = 0.0f;
            if (gk < K) v = Bm[(size_t)gk * N + bn + n];
            Bs[k][n] = v;
        }
        __syncthreads();

#pragma unroll
        for (int k = 0; k < BK; k++) {
            float a[8], b[4];
#pragma unroll
            for (int i = 0; i < 8; i++) a[i] = As[k][ty + 16 * i];
#pragma unroll
            for (int j = 0; j < 4; j++) b[j] = Bs[k][tx + 16 * j];
#pragma unroll
            for (int i = 0; i < 8; i++)
#pragma unroll
                for (int j = 0; j < 4; j++) acc[i][j] = fmaf(a[i], b[j], acc[i][j]);
        }
        __syncthreads();
    }

#pragma unroll
    for (int i = 0; i < 8; i++) {
        int m = bm + ty + 16 * i;
        if (m >= M) continue;
#pragma unroll
        for (int j = 0; j < 4; j++) {
            int n = bn + tx + 16 * j;
            if (n >= N) continue;
            float v = acc[i][j];
            if (HASBIAS) v += bias[n];
            if (ACT == 1) v = sigmoidf_(v);
            C[(size_t)m * N + n] = v;
        }
    }
}

// ---------------- helpers ----------------
__global__ void zero_state_kernel() {
    int i = blockIdx.x * blockDim.x + threadIdx.x;
    if (i < R_ * H_) { g_eh[i] = 0.0f; g_ec[i] = 0.0f; g_dh[i] = 0.0f; }
}

__global__ void concat_w_kernel(const float* __restrict__ Wq, const float* __restrict__ Wk,
                                const float* __restrict__ Wv, float* __restrict__ Wc) {
    int idx = blockIdx.x * blockDim.x + threadIdx.x;   // H * 3H
    if (idx >= H_ * 3 * H_) return;
    int k = idx / (3 * H_);
    int n = idx - k * (3 * H_);
    const float* src = (n < H_) ? Wq : ((n < 2 * H_) ? Wk : Wv);
    Wc[idx] = src[k * H_ + (n & (H_ - 1))];
}

// attention over 4 spatial neighbors (+2,+1,-1,-2); zero-padded OOB -> exact score 0.
__global__ void attn_kernel() {
    int gt = blockIdx.x * blockDim.x + threadIdx.x;
    int warp = gt >> 5;
    int lane = gt & 31;
    if (warp >= R_ * NH_) return;
    int head = warp & (NH_ - 1);
    int r = warp >> 3;
    int s = r & (S_ - 1);
    const float scale = 0.17677669529663687f;   // 1/sqrt(32)

    float qv = g_qkv[(size_t)r * 768 + head * DK_ + lane];
    const int offs[4] = {2, 1, -1, -2};
    float sc[4];
#pragma unroll
    for (int n = 0; n < 4; n++) {
        int sn = s + offs[n];
        float d = 0.0f;
        if (sn >= 0 && sn < S_) {
            int rn = r + offs[n];
            d = qv * g_qkv[(size_t)rn * 768 + 256 + head * DK_ + lane];
        }
        sc[n] = warp_sum(d) * scale;   // 0 for OOB (still in softmax, matches ref)
    }
    float mx = fmaxf(fmaxf(sc[0], sc[1]), fmaxf(sc[2], sc[3]));
    float e[4], sum = 0.0f;
#pragma unroll
    for (int n = 0; n < 4; n++) { e[n] = __expf(sc[n] - mx); sum += e[n]; }
    float inv = 1.0f / sum;
    float acc = 0.0f;
#pragma unroll
    for (int n = 0; n < 4; n++) {
        int sn = s + offs[n];
        if (sn >= 0 && sn < S_) {
            int rn = r + offs[n];
            acc = fmaf(e[n] * inv, g_qkv[(size_t)rn * 768 + 512 + head * DK_ + lane], acc);
        }
    }
    g_ctx[(size_t)r * H_ + head * DK_ + lane] = acc;
}

// assemble [x(3) | eh(256) | ctx(256)] -> g_acat (K = 515)
__global__ void assemble_enc_kernel(const float* __restrict__ input, int t) {
    int idx = blockIdx.x * blockDim.x + threadIdx.x;
    const int K = F_ + 2 * H_;   // 515
    if (idx >= R_ * K) return;
    int r = idx / K;
    int c = idx - r * K;
    int b = r >> 7, s = r & (S_ - 1);
    float v;
    if (c < F_)            v = input[(((size_t)b * T_ + t) * S_ + s) * F_ + c];
    else if (c < F_ + H_)  v = g_eh[(size_t)r * H_ + (c - F_)];
    else                   v = g_ctx[(size_t)r * H_ + (c - F_ - H_)];
    g_acat[idx] = v;
}

// assemble [code | dh | ctx] -> g_acat (K = 768)
__global__ void assemble_dec_kernel() {
    int idx = blockIdx.x * blockDim.x + threadIdx.x;
    const int K = 3 * H_;
    if (idx >= R_ * K) return;
    int r = idx / K;
    int c = idx - r * K;
    float v;
    if (c < H_)            v = g_code[(size_t)r * H_ + c];
    else if (c < 2 * H_)   v = g_dh[(size_t)r * H_ + (c - H_)];
    else                   v = g_ctx[(size_t)r * H_ + (c - 2 * H_)];
    g_acat[idx] = v;
}

// LSTM gates: z=[i|f|g|o] (stride 1024). enc writes c; dec discards c (c_in==h_out==dh ok, elementwise)
template<bool WRITE_C>
__global__ void lstm_kernel(const float* __restrict__ c_in, float* __restrict__ h_out,
                            float* __restrict__ c_out) {
    int idx = blockIdx.x * blockDim.x + threadIdx.x;
    if (idx >= R_ * H_) return;
    int r = idx >> 8;
    int j = idx & (H_ - 1);
    const float* zr = g_z + (size_t)r * (4 * H_);
    float ig = sigmoidf_(zr[j]);
    float fg = sigmoidf_(zr[H_ + j]);
    float gg = tanhf(zr[2 * H_ + j]);
    float og = sigmoidf_(zr[3 * H_ + j]);
    float c = fg * c_in[idx] + ig * gg;
    h_out[idx] = og * tanhf(c);
    if (WRITE_C) c_out[idx] = c;
}

// out[r] = dot(dh[r,:], out_W) + out_b  (warp per row)
__global__ void out_gemv_kernel(const float* __restrict__ W, const float* __restrict__ bsc) {
    int gt = blockIdx.x * blockDim.x + threadIdx.x;
    int warp = gt >> 5;
    int lane = gt & 31;
    if (warp >= R_) return;
    float s = 0.0f;
#pragma unroll
    for (int j = 0; j < H_; j += 32) s = fmaf(g_dh[(size_t)warp * H_ + j + lane], W[j + lane], s);
    s = warp_sum(s);
    if (lane == 0) g_outv[warp] = s + bsc[0];
}

__global__ void write_out_kernel(const float* __restrict__ input, float* __restrict__ dout, int t) {
    int r = blockIdx.x * blockDim.x + threadIdx.x;
    if (r >= R_) return;
    int b = r >> 7, s = r & (S_ - 1);
    float o = g_outv[r];
    float In = (s == 0) ? input[(((size_t)b * T_ + (t + 1)) * S_ + 0) * F_ + 1] : g_outv[r - 1];
    float num = input[(((size_t)b * T_ + t) * S_ + s) * F_ + 2] + In - o;
    size_t base = (((size_t)b * (T_ - TP_ - 1) + (t - TP_)) * S_ + s) * 3;
    dout[base + 0] = o;
    dout[base + 1] = In;
    dout[base + 2] = num;
}

// ---------------- host side ----------------
static void sgemm(const float* A, const float* B, const float* bias, float* C,
                  int M, int N, int K, int act) {
    dim3 grid((N + 63) / 64, (M + 127) / 128);
    if (bias) {
        if (act == 1) sgemm_kernel<1, true><<<grid, 256>>>(A, B, bias, C, M, N, K);
        else          sgemm_kernel<0, true><<<grid, 256>>>(A, B, bias, C, M, N, K);
    } else {
        sgemm_kernel<0, false><<<grid, 256>>>(A, B, nullptr, C, M, N, K);
    }
}

extern "C" void kernel_launch(void* const* d_in, const int* in_sizes, int n_in,
                              void* d_out, int out_size) {
    const float* input = (const float*)d_in[0];
    const float* eWq = (const float*)d_in[1];
    const float* eWk = (const float*)d_in[2];
    const float* eWv = (const float*)d_in[3];
    const float* eWg = (const float*)d_in[4];
    const float* ebg = (const float*)d_in[5];
    const float* dWq = (const float*)d_in[6];
    const float* dWk = (const float*)d_in[7];
    const float* dWv = (const float*)d_in[8];
    const float* dWg = (const float*)d_in[9];
    const float* dbg = (const float*)d_in[10];
    const float* embW = (const float*)d_in[11];
    const float* embb = (const float*)d_in[12];
    const float* outW = (const float*)d_in[13];
    const float* outb = (const float*)d_in[14];
    float* dout = (float*)d_out;

    float *p_eh, *p_ec, *p_dh, *p_qkv, *p_ctx, *p_acat, *p_z, *p_code, *p_We, *p_Wd;
    cudaGetSymbolAddress((void**)&p_eh,   g_eh);
    cudaGetSymbolAddress((void**)&p_ec,   g_ec);
    cudaGetSymbolAddress((void**)&p_dh,   g_dh);
    cudaGetSymbolAddress((void**)&p_qkv,  g_qkv);
    cudaGetSymbolAddress((void**)&p_ctx,  g_ctx);
    cudaGetSymbolAddress((void**)&p_acat, g_acat);
    cudaGetSymbolAddress((void**)&p_z,    g_z);
    cudaGetSymbolAddress((void**)&p_code, g_code);
    cudaGetSymbolAddress((void**)&p_We,   g_Wqkv_e);
    cudaGetSymbolAddress((void**)&p_Wd,   g_Wqkv_d);

    // reset recurrent state + build fused QKV weights (part of the graph, cheap)
    zero_state_kernel<<<(R_ * H_ + 255) / 256, 256>>>();
    concat_w_kernel<<<(H_ * 3 * H_ + 255) / 256, 256>>>(eWq, eWk, eWv, p_We);
    concat_w_kernel<<<(H_ * 3 * H_ + 255) / 256, 256>>>(dWq, dWk, dWv, p_Wd);

    const int KE = F_ + 2 * H_;   // 515
    const int KD = 3 * H_;        // 768

    for (int t = 0; t < T_ - 1; t++) {
        // ---- encoder ----
        sgemm(p_eh, p_We, nullptr, p_qkv, R_, 3 * H_, H_, 0);                 // [q|k|v]
        attn_kernel<<<(R_ * NH_ * 32 + 255) / 256, 256>>>();                  // -> g_ctx
        assemble_enc_kernel<<<(R_ * KE + 255) / 256, 256>>>(input, t);        // -> g_acat
        sgemm(p_acat, eWg, ebg, p_z, R_, 4 * H_, KE, 0);                      // gates
        lstm_kernel<true><<<(R_ * H_ + 255) / 256, 256>>>(p_ec, p_eh, p_ec);  // eh, ec
        sgemm(p_eh, embW, embb, p_code, R_, H_, H_, 1);                       // code = sigmoid(...)

        // ---- decoder (uses old dh for attention; c = old dh) ----
        sgemm(p_dh, p_Wd, nullptr, p_qkv, R_, 3 * H_, H_, 0);
        attn_kernel<<<(R_ * NH_ * 32 + 255) / 256, 256>>>();
        assemble_dec_kernel<<<(R_ * KD + 255) / 256, 256>>>();
        sgemm(p_acat, dWg, dbg, p_z, R_, 4 * H_, KD, 0);
        lstm_kernel<false><<<(R_ * H_ + 255) / 256, 256>>>(p_dh, p_dh, nullptr);

        // ---- output (only needed for t >= TP; out does not feed the recurrence) ----
        if (t >= TP_) {
            out_gemv_kernel<<<(R_ * 32 + 255) / 256, 256>>>(outW, outb);
            write_out_kernel<<<(R_ + 255) / 256, 256>>>(input, dout, t);
        }
    }
}

// round 5
// speedup vs baseline: 2.0614x; 2.0614x over previous
#include <cuda_runtime.h>
#include <math.h>

#define B_  16
#define T_  32
#define S_  128
#define F_  3
#define H_  256
#define NH_ 8
#define DK_ 32
#define TP_ 4
#define R_  2048   // B_*S_ rows per GEMM

// ---------------- device scratch (no allocations allowed) ----------------
__device__ float g_eh[2][R_*H_];      // ping-pong encoder h
__device__ float g_ec[R_*H_];
__device__ float g_dh[2][R_*H_];      // ping-pong decoder h
__device__ float g_qkv[R_*768];       // [q|k|v] per row, stride 768
__device__ float g_ctx[R_*H_];
__device__ float g_code[R_*H_];
__device__ float g_We[H_*768];        // fused enc Wq|Wk|Wv
__device__ float g_Wd[H_*768];        // fused dec Wq|Wk|Wv
__device__ float g_Wge[(F_+2*H_)*4*H_];  // permuted enc gate weights (515 x 1024)
__device__ float g_Wgd[(3*H_)*4*H_];     // permuted dec gate weights (768 x 1024)
__device__ float g_bge[4*H_];
__device__ float g_bgd[4*H_];

__device__ __forceinline__ float sigmoidf_(float x) { return 1.0f / (1.0f + __expf(-x)); }

__device__ __forceinline__ float warp_sum(float v) {
    v += __shfl_xor_sync(0xffffffffu, v, 16);
    v += __shfl_xor_sync(0xffffffffu, v, 8);
    v += __shfl_xor_sync(0xffffffffu, v, 4);
    v += __shfl_xor_sync(0xffffffffu, v, 2);
    v += __shfl_xor_sync(0xffffffffu, v, 1);
    return v;
}

// ---------------- segmented A loader ----------------
// AMODE 0: plain A0 with ld=K
// AMODE 1: encoder gates: [x(3) | eh(256) | ctx(256)]  (K=515)
// AMODE 2: decoder gates: [code(256) | dh(256) | ctx(256)] (K=768)
template<int AMODE>
__device__ __forceinline__ float loadA(const float* __restrict__ A0,
                                       const float* __restrict__ A1,
                                       const float* __restrict__ A2,
                                       int gm, int gk, int K, int t) {
    if (AMODE == 0) {
        return (gk < K) ? A0[(size_t)gm * K + gk] : 0.0f;
    } else if (AMODE == 1) {
        if (gk >= F_ + 2 * H_) return 0.0f;
        if (gk < F_) {
            int b = gm >> 7, s = gm & (S_ - 1);
            return A0[(((size_t)b * T_ + t) * S_ + s) * F_ + gk];
        }
        if (gk < F_ + H_) return A1[(size_t)gm * H_ + (gk - F_)];
        return A2[(size_t)gm * H_ + (gk - F_ - H_)];
    } else {
        if (gk < H_)     return A0[(size_t)gm * H_ + gk];
        if (gk < 2 * H_) return A1[(size_t)gm * H_ + (gk - H_)];
        return A2[(size_t)gm * H_ + (gk - 2 * H_)];
    }
}

__device__ __forceinline__ void mma_tf32(float* d, const unsigned* a, const unsigned* b) {
    asm volatile(
        "mma.sync.aligned.m16n8k8.row.col.f32.tf32.tf32.f32 "
        "{%0,%1,%2,%3}, {%4,%5,%6,%7}, {%8,%9}, {%0,%1,%2,%3};\n"
        : "+f"(d[0]), "+f"(d[1]), "+f"(d[2]), "+f"(d[3])
        : "r"(a[0]), "r"(a[1]), "r"(a[2]), "r"(a[3]), "r"(b[0]), "r"(b[1]));
}

// ---------------- TF32 tensor-core GEMM ----------------
// C[M=2048, N] = A @ B[K,N], BM=128 BN=64 BK=16, 8 warps (4x2), warp tile 32x32,
// mma m16n8k8 (2x4 tiles per warp). Double-buffered smem, one sync per K-tile.
// EPI 0: raw store   EPI 1: sigmoid(acc+bias)   EPI 2: fused LSTM on permuted gates
template<int AMODE, int EPI>
__global__ __launch_bounds__(256, 2)
void gemm_tf32(const float* __restrict__ A0, const float* __restrict__ A1,
               const float* __restrict__ A2, const float* __restrict__ Bm,
               const float* __restrict__ bias, float* __restrict__ C,
               const float* __restrict__ c_in, float* __restrict__ c_out,
               int N, int K, int t)
{
    __shared__ float As[2][128][20];   // pad 16->20: conflict-free frag loads
    __shared__ float Bs[2][16][72];    // pad 64->72: conflict-free frag loads

    const int tid = threadIdx.x, lane = tid & 31, warp = tid >> 5;
    const int wm = warp >> 1, wn = warp & 1;
    const int q = lane & 3, rsel = lane >> 2;
    const int bm = blockIdx.y * 128, bn = blockIdx.x * 64;

    float acc[2][4][4];
#pragma unroll
    for (int i = 0; i < 2; i++)
#pragma unroll
        for (int j = 0; j < 4; j++)
#pragma unroll
            for (int l = 0; l < 4; l++) acc[i][j][l] = 0.0f;

    const int ntiles = (K + 15) >> 4;
    float ra[8], rb[4];

    // prologue: tile 0
#pragma unroll
    for (int i = 0; i < 8; i++) {
        int idx = tid + i * 256; int m = idx >> 4, k = idx & 15;
        ra[i] = loadA<AMODE>(A0, A1, A2, bm + m, k, K, t);
    }
#pragma unroll
    for (int i = 0; i < 4; i++) {
        int idx = tid + i * 256; int k = idx >> 6, n = idx & 63;
        rb[i] = (k < K) ? Bm[(size_t)k * N + bn + n] : 0.0f;
    }
#pragma unroll
    for (int i = 0; i < 8; i++) { int idx = tid + i * 256; As[0][idx >> 4][idx & 15] = ra[i]; }
#pragma unroll
    for (int i = 0; i < 4; i++) { int idx = tid + i * 256; Bs[0][idx >> 6][idx & 63] = rb[i]; }
    __syncthreads();

    int buf = 0;
    for (int kt = 0; kt < ntiles; kt++) {
        const int k0n = (kt + 1) << 4;
        const bool more = (kt + 1) < ntiles;
        if (more) {
#pragma unroll
            for (int i = 0; i < 8; i++) {
                int idx = tid + i * 256; int m = idx >> 4, k = idx & 15;
                ra[i] = loadA<AMODE>(A0, A1, A2, bm + m, k0n + k, K, t);
            }
#pragma unroll
            for (int i = 0; i < 4; i++) {
                int idx = tid + i * 256; int k = idx >> 6, n = idx & 63;
                rb[i] = (k0n + k < K) ? Bm[(size_t)(k0n + k) * N + bn + n] : 0.0f;
            }
        }
#pragma unroll
        for (int kk = 0; kk < 16; kk += 8) {
            unsigned a[2][4], b[4][2];
#pragma unroll
            for (int tm = 0; tm < 2; tm++) {
                int row = wm * 32 + tm * 16 + rsel;
                a[tm][0] = __float_as_uint(As[buf][row][kk + q]);
                a[tm][1] = __float_as_uint(As[buf][row + 8][kk + q]);
                a[tm][2] = __float_as_uint(As[buf][row][kk + q + 4]);
                a[tm][3] = __float_as_uint(As[buf][row + 8][kk + q + 4]);
            }
#pragma unroll
            for (int tn = 0; tn < 4; tn++) {
                int col = wn * 32 + tn * 8 + rsel;
                b[tn][0] = __float_as_uint(Bs[buf][kk + q][col]);
                b[tn][1] = __float_as_uint(Bs[buf][kk + q + 4][col]);
            }
#pragma unroll
            for (int tm = 0; tm < 2; tm++)
#pragma unroll
                for (int tn = 0; tn < 4; tn++) mma_tf32(acc[tm][tn], a[tm], b[tn]);
        }
        if (more) {
#pragma unroll
            for (int i = 0; i < 8; i++) { int idx = tid + i * 256; As[buf ^ 1][idx >> 4][idx & 15] = ra[i]; }
#pragma unroll
            for (int i = 0; i < 4; i++) { int idx = tid + i * 256; Bs[buf ^ 1][idx >> 6][idx & 63] = rb[i]; }
        }
        __syncthreads();
        buf ^= 1;
    }

    // ---------------- epilogue ----------------
    if (EPI == 0) {
#pragma unroll
        for (int tm = 0; tm < 2; tm++)
#pragma unroll
            for (int tn = 0; tn < 4; tn++) {
                int r0 = bm + wm * 32 + tm * 16 + rsel;
                int col = bn + wn * 32 + tn * 8 + 2 * q;
                C[(size_t)r0 * N + col]           = acc[tm][tn][0];
                C[(size_t)r0 * N + col + 1]       = acc[tm][tn][1];
                C[(size_t)(r0 + 8) * N + col]     = acc[tm][tn][2];
                C[(size_t)(r0 + 8) * N + col + 1] = acc[tm][tn][3];
            }
    } else if (EPI == 1) {
#pragma unroll
        for (int tm = 0; tm < 2; tm++)
#pragma unroll
            for (int tn = 0; tn < 4; tn++) {
                int r0 = bm + wm * 32 + tm * 16 + rsel;
                int col = bn + wn * 32 + tn * 8 + 2 * q;
                float b0 = bias[col], b1 = bias[col + 1];
                C[(size_t)r0 * N + col]           = sigmoidf_(acc[tm][tn][0] + b0);
                C[(size_t)r0 * N + col + 1]       = sigmoidf_(acc[tm][tn][1] + b1);
                C[(size_t)(r0 + 8) * N + col]     = sigmoidf_(acc[tm][tn][2] + b0);
                C[(size_t)(r0 + 8) * N + col + 1] = sigmoidf_(acc[tm][tn][3] + b1);
            }
    } else {
        // permuted gate layout: col j = 4*h + gate, gate order [i,f,g,o].
        // even-q lanes hold (i,f), odd-q partner (lane^1) holds (g,o).
#pragma unroll
        for (int tm = 0; tm < 2; tm++)
#pragma unroll
            for (int tn = 0; tn < 4; tn++) {
                int col = bn + wn * 32 + tn * 8 + 2 * q;
                float b0 = bias[col], b1 = bias[col + 1];
#pragma unroll
                for (int half = 0; half < 2; half++) {
                    int r = bm + wm * 32 + tm * 16 + rsel + half * 8;
                    float v0 = acc[tm][tn][half * 2 + 0] + b0;   // i (even q) / g (odd q)
                    float v1 = acc[tm][tn][half * 2 + 1] + b1;   // f (even q) / o (odd q)
                    float p0 = __shfl_xor_sync(0xffffffffu, v0, 1);
                    float p1 = __shfl_xor_sync(0xffffffffu, v1, 1);
                    if (!(q & 1)) {
                        int h = col >> 2;
                        float cn = sigmoidf_(v1) * c_in[(size_t)r * H_ + h]
                                 + sigmoidf_(v0) * tanhf(p0);
                        float hn = sigmoidf_(p1) * tanhf(cn);
                        C[(size_t)r * H_ + h] = hn;
                        if (c_out) c_out[(size_t)r * H_ + h] = cn;
                    }
                }
            }
    }
}

// ---------------- init / weight prep ----------------
__global__ void zero_state_kernel() {
    int i = blockIdx.x * blockDim.x + threadIdx.x;
    if (i < R_ * H_) { g_eh[0][i] = 0.0f; g_ec[i] = 0.0f; g_dh[0][i] = 0.0f; }
}

__global__ void concat_w_kernel(const float* __restrict__ Wq, const float* __restrict__ Wk,
                                const float* __restrict__ Wv, float* __restrict__ Wc) {
    int idx = blockIdx.x * blockDim.x + threadIdx.x;   // H * 3H
    if (idx >= H_ * 3 * H_) return;
    int k = idx / (3 * H_);
    int n = idx - k * (3 * H_);
    const float* src = (n < H_) ? Wq : ((n < 2 * H_) ? Wk : Wv);
    Wc[idx] = src[k * H_ + (n & (H_ - 1))];
}

// pW[k][4h+g] = W[k][g*256+h]; pb likewise
__global__ void permute_wg_kernel(const float* __restrict__ W, const float* __restrict__ b,
                                  float* __restrict__ pW, float* __restrict__ pb, int K) {
    int idx = blockIdx.x * blockDim.x + threadIdx.x;
    if (idx >= K * 4 * H_) return;
    int k = idx >> 10;
    int n = idx & (4 * H_ - 1);
    int h = n >> 2, g = n & 3;
    pW[idx] = W[(size_t)k * 4 * H_ + g * H_ + h];
    if (idx < 4 * H_) pb[idx] = b[g * H_ + h];
}

// ---------------- attention over 4 spatial neighbors ----------------
__global__ void attn_kernel() {
    int gt = blockIdx.x * blockDim.x + threadIdx.x;
    int warp = gt >> 5;
    int lane = gt & 31;
    if (warp >= R_ * NH_) return;
    int head = warp & (NH_ - 1);
    int r = warp >> 3;
    int s = r & (S_ - 1);
    const float scale = 0.17677669529663687f;   // 1/sqrt(32)

    float qv = g_qkv[(size_t)r * 768 + head * DK_ + lane];
    const int offs[4] = {2, 1, -1, -2};
    float sc[4];
#pragma unroll
    for (int n = 0; n < 4; n++) {
        int sn = s + offs[n];
        float d = 0.0f;
        if (sn >= 0 && sn < S_) {
            int rn = r + offs[n];
            d = qv * g_qkv[(size_t)rn * 768 + 256 + head * DK_ + lane];
        }
        sc[n] = warp_sum(d) * scale;
    }
    float mx = fmaxf(fmaxf(sc[0], sc[1]), fmaxf(sc[2], sc[3]));
    float e[4], sum = 0.0f;
#pragma unroll
    for (int n = 0; n < 4; n++) { e[n] = __expf(sc[n] - mx); sum += e[n]; }
    float inv = 1.0f / sum;
    float accv = 0.0f;
#pragma unroll
    for (int n = 0; n < 4; n++) {
        int sn = s + offs[n];
        if (sn >= 0 && sn < S_) {
            int rn = r + offs[n];
            accv = fmaf(e[n] * inv, g_qkv[(size_t)rn * 768 + 512 + head * DK_ + lane], accv);
        }
    }
    g_ctx[(size_t)r * H_ + head * DK_ + lane] = accv;
}

// ---------------- fused output GEMV + assembly ----------------
__global__ void out_kernel(const float* __restrict__ dh, const float* __restrict__ W,
                           const float* __restrict__ bb, const float* __restrict__ input,
                           float* __restrict__ dout, int t) {
    int gt = blockIdx.x * blockDim.x + threadIdx.x;
    int warp = gt >> 5;
    int lane = gt & 31;
    if (warp >= R_) return;
    int r = warp, b = r >> 7, s = r & (S_ - 1);
    float s0 = 0.0f, s1 = 0.0f;
#pragma unroll
    for (int j = 0; j < H_; j += 32) {
        float w = W[j + lane];
        s0 = fmaf(dh[(size_t)r * H_ + j + lane], w, s0);
        if (s > 0) s1 = fmaf(dh[(size_t)(r - 1) * H_ + j + lane], w, s1);
    }
    s0 = warp_sum(s0);
    s1 = warp_sum(s1);
    if (lane == 0) {
        float o  = s0 + bb[0];
        float In = (s > 0) ? (s1 + bb[0])
                           : input[(((size_t)b * T_ + (t + 1)) * S_ + 0) * F_ + 1];
        float num = input[(((size_t)b * T_ + t) * S_ + s) * F_ + 2] + In - o;
        size_t base = (((size_t)b * (T_ - TP_ - 1) + (t - TP_)) * S_ + s) * 3;
        dout[base + 0] = o;
        dout[base + 1] = In;
        dout[base + 2] = num;
    }
}

// ---------------- host side ----------------
extern "C" void kernel_launch(void* const* d_in, const int* in_sizes, int n_in,
                              void* d_out, int out_size) {
    const float* input = (const float*)d_in[0];
    const float* eWq = (const float*)d_in[1];
    const float* eWk = (const float*)d_in[2];
    const float* eWv = (const float*)d_in[3];
    const float* eWg = (const float*)d_in[4];
    const float* ebg = (const float*)d_in[5];
    const float* dWq = (const float*)d_in[6];
    const float* dWk = (const float*)d_in[7];
    const float* dWv = (const float*)d_in[8];
    const float* dWg = (const float*)d_in[9];
    const float* dbg = (const float*)d_in[10];
    const float* embW = (const float*)d_in[11];
    const float* embb = (const float*)d_in[12];
    const float* outW = (const float*)d_in[13];
    const float* outb = (const float*)d_in[14];
    float* dout = (float*)d_out;

    float *p_eh, *p_ec, *p_dh, *p_qkv, *p_ctx, *p_code;
    float *p_We, *p_Wd, *p_Wge, *p_Wgd, *p_bge, *p_bgd;
    cudaGetSymbolAddress((void**)&p_eh,   g_eh);
    cudaGetSymbolAddress((void**)&p_ec,   g_ec);
    cudaGetSymbolAddress((void**)&p_dh,   g_dh);
    cudaGetSymbolAddress((void**)&p_qkv,  g_qkv);
    cudaGetSymbolAddress((void**)&p_ctx,  g_ctx);
    cudaGetSymbolAddress((void**)&p_code, g_code);
    cudaGetSymbolAddress((void**)&p_We,   g_We);
    cudaGetSymbolAddress((void**)&p_Wd,   g_Wd);
    cudaGetSymbolAddress((void**)&p_Wge,  g_Wge);
    cudaGetSymbolAddress((void**)&p_Wgd,  g_Wgd);
    cudaGetSymbolAddress((void**)&p_bge,  g_bge);
    cudaGetSymbolAddress((void**)&p_bgd,  g_bgd);

    float* eh[2] = { p_eh, p_eh + (size_t)R_ * H_ };
    float* dh[2] = { p_dh, p_dh + (size_t)R_ * H_ };

    const int KE = F_ + 2 * H_;   // 515
    const int KD = 3 * H_;        // 768

    zero_state_kernel<<<(R_ * H_ + 255) / 256, 256>>>();
    concat_w_kernel<<<(H_ * 3 * H_ + 255) / 256, 256>>>(eWq, eWk, eWv, p_We);
    concat_w_kernel<<<(H_ * 3 * H_ + 255) / 256, 256>>>(dWq, dWk, dWv, p_Wd);
    permute_wg_kernel<<<(KE * 4 * H_ + 255) / 256, 256>>>(eWg, ebg, p_Wge, p_bge, KE);
    permute_wg_kernel<<<(KD * 4 * H_ + 255) / 256, 256>>>(dWg, dbg, p_Wgd, p_bgd, KD);

    dim3 grid_qkv(768 / 64, 16), grid_g(1024 / 64, 16), grid_emb(256 / 64, 16);
    int ce = 0, cd = 0;

    for (int t = 0; t < T_ - 1; t++) {
        // ---- encoder ----
        gemm_tf32<0, 0><<<grid_qkv, 256>>>(eh[ce], nullptr, nullptr, p_We, nullptr,
                                           p_qkv, nullptr, nullptr, 768, H_, 0);
        attn_kernel<<<(R_ * NH_ * 32 + 255) / 256, 256>>>();
        gemm_tf32<1, 2><<<grid_g, 256>>>(input, eh[ce], p_ctx, p_Wge, p_bge,
                                         eh[ce ^ 1], p_ec, p_ec, 4 * H_, KE, t);
        ce ^= 1;
        gemm_tf32<0, 1><<<grid_emb, 256>>>(eh[ce], nullptr, nullptr, embW, embb,
                                           p_code, nullptr, nullptr, H_, H_, 0);

        // ---- decoder (attention + cell use old dh; c = old dh) ----
        gemm_tf32<0, 0><<<grid_qkv, 256>>>(dh[cd], nullptr, nullptr, p_Wd, nullptr,
                                           p_qkv, nullptr, nullptr, 768, H_, 0);
        attn_kernel<<<(R_ * NH_ * 32 + 255) / 256, 256>>>();
        gemm_tf32<2, 2><<<grid_g, 256>>>(p_code, dh[cd], p_ctx, p_Wgd, p_bgd,
                                         dh[cd ^ 1], dh[cd], nullptr, 4 * H_, KD, 0);
        cd ^= 1;

        // ---- output ----
        if (t >= TP_) {
            out_kernel<<<(R_ * 32 + 255) / 256, 256>>>(dh[cd], outW, outb, input, dout, t);
        }
    }
}